// round 9
// baseline (speedup 1.0000x reference)
#include <cuda_runtime.h>
#include <math.h>

#define NG    2048
#define W     128
#define H     128
#define EPSV  1e-4f
#define NEARV 0.3f
#define TAU   18.2f       // cull threshold on folded exponent

// render tiling
#define RTW   8           // tile width (px)
#define RTH   8           // tile height (px)
#define RPPT  (RTW*RTH)   // 64 px per tile
#define RNSUB 8           // depth chunks
#define RBT   (RNSUB*RPPT) // 512 threads
#define NTX   (W/RTW)     // 16
#define NTY   (H/RTH)     // 16
#define NCAP  1024        // max staged survivors per tile (unreachable in practice)

// ---------------- device scratch ----------------
// unsorted (prep) / sorted (sortgather)
__device__ float4 d_ga [NG];   // u, v, A, B
__device__ float4 d_gb [NG];   // C, L, r, g
__device__ float4 d_cu [NG];   // u, v, hx, hy
__device__ float  d_bb [NG];   // b
__device__ float  d_key[NG];   // depth key
__device__ float4 d_sga[NG];
__device__ float4 d_sgb[NG];
__device__ float4 d_scu[NG];
__device__ float  d_sbb[NG];

__device__ __forceinline__ float sigmoidf_(float x) {
    return 1.0f / (1.0f + expf(-x));
}

// ---------------- 1) per-gaussian preprocessing (32 blocks x 64 thr) ----------------
__global__ void __launch_bounds__(64) prep_kernel(
        const float* __restrict__ pos,
        const float* __restrict__ rgb,
        const float* __restrict__ opa,
        const float* __restrict__ quat,
        const float* __restrict__ scale,
        const float* __restrict__ rot,
        const float* __restrict__ tran)
{
    int n = blockIdx.x * 64 + threadIdx.x;
    if (n >= NG) return;

    float Rw[9];
#pragma unroll
    for (int i = 0; i < 9; i++) Rw[i] = __ldg(&rot[i]);
    float t0 = __ldg(&tran[0]), t1 = __ldg(&tran[1]), t2 = __ldg(&tran[2]);

    float p0 = __ldg(&pos[n*3+0]), p1 = __ldg(&pos[n*3+1]), p2 = __ldg(&pos[n*3+2]);
    float x = Rw[0]*p0 + Rw[1]*p1 + Rw[2]*p2 + t0;
    float y = Rw[3]*p0 + Rw[4]*p1 + Rw[5]*p2 + t1;
    float z = Rw[6]*p0 + Rw[7]*p1 + Rw[8]*p2 + t2;

    float r = sqrtf(x*x + y*y + z*z);
    float iz  = 1.0f / z;
    float u = x * iz, v = y * iz;
    float iz2 = iz * iz;

    float M00 = iz*Rw[0] - x*iz2*Rw[6];
    float M01 = iz*Rw[1] - x*iz2*Rw[7];
    float M02 = iz*Rw[2] - x*iz2*Rw[8];
    float M10 = iz*Rw[3] - y*iz2*Rw[6];
    float M11 = iz*Rw[4] - y*iz2*Rw[7];
    float M12 = iz*Rw[5] - y*iz2*Rw[8];

    float4 q4 = __ldg((const float4*)(quat + n*4));
    float qw = q4.x, qx = q4.y, qy = q4.z, qz = q4.w;
    float qn = rsqrtf(qw*qw + qx*qx + qy*qy + qz*qz);
    qw *= qn; qx *= qn; qy *= qn; qz *= qn;
    float R00 = 1.0f - 2.0f*(qy*qy + qz*qz);
    float R01 = 2.0f*(qx*qy - qw*qz);
    float R02 = 2.0f*(qx*qz + qw*qy);
    float R10 = 2.0f*(qx*qy + qw*qz);
    float R11 = 1.0f - 2.0f*(qx*qx + qz*qz);
    float R12 = 2.0f*(qy*qz - qw*qx);
    float R20 = 2.0f*(qx*qz - qw*qy);
    float R21 = 2.0f*(qy*qz + qw*qx);
    float R22 = 1.0f - 2.0f*(qx*qx + qy*qy);

    float s0 = fabsf(__ldg(&scale[n*3+0])) + 1e-4f;
    float s1 = fabsf(__ldg(&scale[n*3+1])) + 1e-4f;
    float s2 = fabsf(__ldg(&scale[n*3+2])) + 1e-4f;
    float q0 = s0*s0, q1 = s1*s1, q2 = s2*s2;

    float c00 = R00*R00*q0 + R01*R01*q1 + R02*R02*q2;
    float c01 = R00*R10*q0 + R01*R11*q1 + R02*R12*q2;
    float c02 = R00*R20*q0 + R01*R21*q1 + R02*R22*q2;
    float c11 = R10*R10*q0 + R11*R11*q1 + R12*R12*q2;
    float c12 = R10*R20*q0 + R11*R21*q1 + R12*R22*q2;
    float c22 = R20*R20*q0 + R21*R21*q1 + R22*R22*q2;

    float v00 = c00*M00 + c01*M01 + c02*M02;
    float v01 = c01*M00 + c11*M01 + c12*M02;
    float v02 = c02*M00 + c12*M01 + c22*M02;
    float v10 = c00*M10 + c01*M11 + c02*M12;
    float v11 = c01*M10 + c11*M11 + c12*M12;
    float v12 = c02*M10 + c12*M11 + c22*M12;

    float a  = M00*v00 + M01*v01 + M02*v02 + EPSV;   // Sigma_xx
    float b  = M00*v10 + M01*v11 + M02*v12;
    float cc = M10*v10 + M11*v11 + M12*v12 + EPSV;   // Sigma_yy

    float det  = a*cc - b*b;
    float idet = 1.0f / det;
    float A = -0.5f * cc * idet;
    float B =  b * idet;
    float C = -0.5f * a  * idet;

    float opa_s = sigmoidf_(__ldg(&opa[n]));
    float L = (z > NEARV) ? logf(opa_s) : -1e30f;

    float tau = TAU + L;
    float hx, hy;
    if (tau > 0.0f) {
        hx = sqrtf(2.0f * tau * a);
        hy = sqrtf(2.0f * tau * cc);
    } else {
        hx = -1e30f; hy = -1e30f;   // always culled
    }

    float cr = sigmoidf_(__ldg(&rgb[n*3+0]));
    float cg = sigmoidf_(__ldg(&rgb[n*3+1]));
    float cb = sigmoidf_(__ldg(&rgb[n*3+2]));

    d_cu [n] = make_float4(u, v, hx, hy);
    d_ga [n] = make_float4(u, v, A, B);
    d_gb [n] = make_float4(C, L, cr, cg);
    d_bb [n] = cb;
    d_key[n] = r;
}

// ---------------- 2) global stable rank-sort + gather (64 blk x 256 thr) ----------------
// warp per 4 gaussians; uniform trip counts -> shfl safe.
__global__ void __launch_bounds__(256) sortgather_kernel()
{
    __shared__ float sk[NG];
    int t = threadIdx.x;
    for (int i = t; i < NG; i += 256) sk[i] = __ldg(&d_key[i]);
    __syncthreads();

    int wid = t >> 5, lane = t & 31;
#pragma unroll
    for (int ii = 0; ii < 4; ii++) {
        int i = (blockIdx.x * 8 + wid) * 4 + ii;   // original index
        float ki = sk[i];
        int c = 0;
#pragma unroll 8
        for (int j = lane; j < NG; j += 32) {      // 64 iters, uniform
            float kj = sk[j];
            c += (int)((kj < ki) | ((kj == ki) & (j < i)));   // stable ties
        }
#pragma unroll
        for (int o = 16; o; o >>= 1) c += __shfl_xor_sync(0xFFFFFFFFu, c, o);
        if      (lane == 0) d_sga[c] = d_ga[i];
        else if (lane == 1) d_sgb[c] = d_gb[i];
        else if (lane == 2) d_scu[c] = d_cu[i];
        else if (lane == 3) d_sbb[c] = d_bb[i];
    }
}

// ---------------- 3) per-tile compact + chunked composite (256 blk x 512 thr) ----------------
__global__ void __launch_bounds__(RBT) render_kernel(float* __restrict__ out)
{
    __shared__ float4 sga [NCAP];            // 16KB
    __shared__ float4 sgb [NCAP];            // 16KB
    __shared__ float  sbb [NCAP];            //  4KB
    __shared__ float4 part[RNSUB*RPPT];      //  8KB
    __shared__ int    warpcnt[16];

    const int t    = threadIdx.x;
    const int wid  = t >> 5, lane = t & 31;
    const int tx   = blockIdx.x, ty = blockIdx.y;

    const float xmin = (tx*RTW         - 63.5f) * (1.0f/128.0f);
    const float xmax = (tx*RTW + RTW-1 - 63.5f) * (1.0f/128.0f);
    const float ymin = (ty*RTH         - 63.5f) * (1.0f/128.0f);
    const float ymax = (ty*RTH + RTH-1 - 63.5f) * (1.0f/128.0f);

    // ---- order-preserving compaction + fused staging ----
    int base = 0;
#pragma unroll
    for (int p = 0; p < NG/RBT; p++) {             // 4 passes, uniform
        int i = p*RBT + t;
        float4 cv = __ldg(&d_scu[i]);
        bool keep = (cv.x - cv.z <= xmax) && (cv.x + cv.z >= xmin) &&
                    (cv.y - cv.w <= ymax) && (cv.y + cv.w >= ymin);
        unsigned m = __ballot_sync(0xFFFFFFFFu, keep);
        int wofs = __popc(m & ((1u << lane) - 1u));
        if (lane == 0) warpcnt[wid] = __popc(m);
        __syncthreads();
        if (t < 32) {                               // warp 0, full mask
            int v = (t < 16) ? warpcnt[t] : 0;
#pragma unroll
            for (int o = 1; o < 32; o <<= 1) {
                int u2 = __shfl_up_sync(0xFFFFFFFFu, v, o);
                if (lane >= o) v += u2;
            }
            if (t < 16) warpcnt[t] = v;             // inclusive scan
        }
        __syncthreads();
        int slot = base + (wid ? warpcnt[wid-1] : 0) + wofs;
        if (keep && slot < NCAP) {
            sga[slot] = __ldg(&d_sga[i]);
            sgb[slot] = __ldg(&d_sgb[i]);
            sbb[slot] = __ldg(&d_sbb[i]);
        }
        base += warpcnt[15];
        __syncthreads();
    }
    const int N = (base < NCAP) ? base : NCAP;

    // ---- chunked branch-free composite ----
    const int sub = t >> 6;            // depth chunk 0..7
    const int pix = t & (RPPT-1);      // pixel 0..63
    const int x = tx*RTW + (pix & (RTW-1));
    const int y = ty*RTH + (pix >> 3);
    const float px = (x - 63.5f) * (1.0f/128.0f);
    const float py = (y - 63.5f) * (1.0f/128.0f);

    const int Nc = (N + RNSUB - 1) / RNSUB;
    const int k0 = sub * Nc;
    int k1 = k0 + Nc; if (k1 > N) k1 = N;

    float T = 1.0f, cr = 0.0f, cg = 0.0f, cb = 0.0f;
#pragma unroll 4
    for (int k = k0; k < k1; k++) {
        float4 ga = sga[k];
        float4 gb = sgb[k];
        float dx = px - ga.x;
        float dy = py - ga.y;
        float pw = fmaf(fmaf(ga.z, dx, ga.w * dy), dx, fmaf(gb.x * dy, dy, gb.y));
        float al = fminf(__expf(pw), 0.99f);
        float wg = T * al;
        cr = fmaf(wg, gb.z, cr);
        cg = fmaf(wg, gb.w, cg);
        cb = fmaf(wg, sbb[k], cb);
        T -= wg;
    }
    part[sub * RPPT + pix] = make_float4(cr, cg, cb, T);
    __syncthreads();

    // ---- exact recombination + store ----
    if (t < RPPT) {
        float P = 1.0f, r = 0.0f, g = 0.0f, b = 0.0f;
#pragma unroll
        for (int s = 0; s < RNSUB; s++) {
            float4 qq = part[s * RPPT + t];
            r = fmaf(P, qq.x, r);
            g = fmaf(P, qq.y, g);
            b = fmaf(P, qq.z, b);
            P *= qq.w;
        }
        int xx = tx*RTW + (t & (RTW-1));
        int yy = ty*RTH + (t >> 3);
        int o = (yy * W + xx) * 3;
        out[o + 0] = r;
        out[o + 1] = g;
        out[o + 2] = b;
    }
}

extern "C" void kernel_launch(void* const* d_in, const int* in_sizes, int n_in,
                              void* d_out, int out_size)
{
    const float* pos   = (const float*)d_in[0];
    const float* rgb   = (const float*)d_in[1];
    const float* opa   = (const float*)d_in[2];
    const float* quat  = (const float*)d_in[3];
    const float* scale = (const float*)d_in[4];
    const float* rot   = (const float*)d_in[5];
    const float* tran  = (const float*)d_in[6];
    float* out = (float*)d_out;

    prep_kernel<<<32, 64>>>(pos, rgb, opa, quat, scale, rot, tran);
    sortgather_kernel<<<64, 256>>>();
    render_kernel<<<dim3(NTX, NTY), RBT>>>(out);
}

// round 10
// speedup vs baseline: 1.0184x; 1.0184x over previous
#include <cuda_runtime.h>
#include <math.h>

#define NG    2048
#define W     128
#define H     128
#define EPSV  1e-4f
#define NEARV 0.3f
#define TAU   18.2f

#define NBLK  128         // <= 148 SMs: all blocks co-resident (1/SM) -> barrier safe
#define BT    512         // threads per block (16 warps)
#define GPB   (NG/NBLK)   // 16 gaussians prepped per block (by warp 0 lanes)
#define WPB   (BT/32)     // 16 warps -> 2048 warps total = 1 warp per gaussian

// render tiling: 8x8 px, 256 tiles, 2 tiles per block
#define RTW   8
#define RTH   8
#define RPPT  (RTW*RTH)   // 64
#define RNSUB 8           // depth chunks (8*64 = 512 threads)
#define NTX   (W/RTW)     // 16
#define TILES (NTX*(H/RTH)) // 256
#define NCAP  1024        // staged survivor cap (worst tile ~300)

// ---------------- device scratch ----------------
__device__ float4 d_ga [NG];   // unsorted u,v,A,B
__device__ float4 d_gb [NG];   // unsorted C,L,r,g
__device__ float4 d_cu [NG];   // unsorted u,v,hx,hy
__device__ float  d_bb [NG];   // unsorted b
__device__ float  d_key[NG];   // depth key
__device__ float4 d_sga[NG];   // sorted
__device__ float4 d_sgb[NG];
__device__ float4 d_scu[NG];
__device__ float  d_sbb[NG];
__device__ unsigned bar_cnt;   // monotonic grid-barrier counter (never reset)

__device__ __forceinline__ float sigmoidf_(float x) {
    return 1.0f / (1.0f + expf(-x));
}

__device__ __forceinline__ void grid_barrier() {
    __syncthreads();
    if (threadIdx.x == 0) {
        __threadfence();
        unsigned arrival = atomicAdd(&bar_cnt, 1u);
        unsigned target  = (arrival / NBLK + 1u) * NBLK;
        while (*((volatile unsigned*)&bar_cnt) < target) { }
        __threadfence();
    }
    __syncthreads();
}

// static smem: 16K + 16K + 4K + 8K = 44KB  (skey aliases sga: dead before sga written)
__shared__ float4 sga [NCAP];
__shared__ float4 sgb [NCAP];
__shared__ float  sbb [NCAP];
__shared__ float4 part[RNSUB*RPPT];
__shared__ int    warpcnt[WPB];

__global__ void __launch_bounds__(BT, 1)
splat_kernel(const float* __restrict__ pos,
             const float* __restrict__ rgb,
             const float* __restrict__ opa,
             const float* __restrict__ quat,
             const float* __restrict__ scale,
             const float* __restrict__ rot,
             const float* __restrict__ tran,
             float* __restrict__ out)
{
    const int t    = threadIdx.x;
    const int wid  = t >> 5, lane = t & 31;
    const int bid  = blockIdx.x;
    float* skey = (float*)sga;          // alias: 2048 floats, used only in phase B

    // ================= phase A: distributed prep (warp 0, 16 lanes) =================
    if (t < GPB) {
        const int n = bid + NBLK * t;   // gaussian index

        float Rw[9];
#pragma unroll
        for (int i = 0; i < 9; i++) Rw[i] = __ldg(&rot[i]);
        float t0 = __ldg(&tran[0]), t1 = __ldg(&tran[1]), t2 = __ldg(&tran[2]);

        float p0 = __ldg(&pos[n*3+0]), p1 = __ldg(&pos[n*3+1]), p2 = __ldg(&pos[n*3+2]);
        float x = Rw[0]*p0 + Rw[1]*p1 + Rw[2]*p2 + t0;
        float y = Rw[3]*p0 + Rw[4]*p1 + Rw[5]*p2 + t1;
        float z = Rw[6]*p0 + Rw[7]*p1 + Rw[8]*p2 + t2;

        float r = sqrtf(x*x + y*y + z*z);
        float iz  = 1.0f / z;
        float u = x * iz, v = y * iz;
        float iz2 = iz * iz;

        float M00 = iz*Rw[0] - x*iz2*Rw[6];
        float M01 = iz*Rw[1] - x*iz2*Rw[7];
        float M02 = iz*Rw[2] - x*iz2*Rw[8];
        float M10 = iz*Rw[3] - y*iz2*Rw[6];
        float M11 = iz*Rw[4] - y*iz2*Rw[7];
        float M12 = iz*Rw[5] - y*iz2*Rw[8];

        float4 q4 = __ldg((const float4*)(quat + n*4));
        float qw = q4.x, qx = q4.y, qy = q4.z, qz = q4.w;
        float qn = rsqrtf(qw*qw + qx*qx + qy*qy + qz*qz);
        qw *= qn; qx *= qn; qy *= qn; qz *= qn;
        float R00 = 1.0f - 2.0f*(qy*qy + qz*qz);
        float R01 = 2.0f*(qx*qy - qw*qz);
        float R02 = 2.0f*(qx*qz + qw*qy);
        float R10 = 2.0f*(qx*qy + qw*qz);
        float R11 = 1.0f - 2.0f*(qx*qx + qz*qz);
        float R12 = 2.0f*(qy*qz - qw*qx);
        float R20 = 2.0f*(qx*qz - qw*qy);
        float R21 = 2.0f*(qy*qz + qw*qx);
        float R22 = 1.0f - 2.0f*(qx*qx + qy*qy);

        float s0 = fabsf(__ldg(&scale[n*3+0])) + 1e-4f;
        float s1 = fabsf(__ldg(&scale[n*3+1])) + 1e-4f;
        float s2 = fabsf(__ldg(&scale[n*3+2])) + 1e-4f;
        float q0 = s0*s0, q1 = s1*s1, q2 = s2*s2;

        float c00 = R00*R00*q0 + R01*R01*q1 + R02*R02*q2;
        float c01 = R00*R10*q0 + R01*R11*q1 + R02*R12*q2;
        float c02 = R00*R20*q0 + R01*R21*q1 + R02*R22*q2;
        float c11 = R10*R10*q0 + R11*R11*q1 + R12*R12*q2;
        float c12 = R10*R20*q0 + R11*R21*q1 + R12*R22*q2;
        float c22 = R20*R20*q0 + R21*R21*q1 + R22*R22*q2;

        float v00 = c00*M00 + c01*M01 + c02*M02;
        float v01 = c01*M00 + c11*M01 + c12*M02;
        float v02 = c02*M00 + c12*M01 + c22*M02;
        float v10 = c00*M10 + c01*M11 + c02*M12;
        float v11 = c01*M10 + c11*M11 + c12*M12;
        float v12 = c02*M10 + c12*M11 + c22*M12;

        float a  = M00*v00 + M01*v01 + M02*v02 + EPSV;
        float b  = M00*v10 + M01*v11 + M02*v12;
        float cc = M10*v10 + M11*v11 + M12*v12 + EPSV;

        float det  = a*cc - b*b;
        float idet = 1.0f / det;
        float A = -0.5f * cc * idet;
        float B =  b * idet;
        float C = -0.5f * a  * idet;

        float opa_s = sigmoidf_(__ldg(&opa[n]));
        float L = (z > NEARV) ? logf(opa_s) : -1e30f;

        float tau = TAU + L;
        float hx, hy;
        if (tau > 0.0f) {
            hx = sqrtf(2.0f * tau * a);
            hy = sqrtf(2.0f * tau * cc);
        } else {
            hx = -1e30f; hy = -1e30f;
        }

        float cr = sigmoidf_(__ldg(&rgb[n*3+0]));
        float cg = sigmoidf_(__ldg(&rgb[n*3+1]));
        float cb = sigmoidf_(__ldg(&rgb[n*3+2]));

        d_cu [n] = make_float4(u, v, hx, hy);
        d_ga [n] = make_float4(u, v, A, B);
        d_gb [n] = make_float4(C, L, cr, cg);
        d_bb [n] = cb;
        d_key[n] = r;
    }

    grid_barrier();

    // ================= phase B: global stable rank-sort (1 warp / gaussian) =========
    for (int i = t; i < NG; i += BT) skey[i] = d_key[i];
    __syncthreads();
    {
        const int g = bid * WPB + wid;       // this warp's gaussian
        float ki = skey[g];
        int c = 0;
#pragma unroll 8
        for (int j = lane; j < NG; j += 32) {          // 64 iters, uniform
            float kj = skey[j];
            c += (int)((kj < ki) | ((kj == ki) & (j < g)));
        }
#pragma unroll
        for (int o = 16; o; o >>= 1) c += __shfl_xor_sync(0xFFFFFFFFu, c, o);
        if      (lane == 0) d_sga[c] = d_ga[g];
        else if (lane == 1) d_sgb[c] = d_gb[g];
        else if (lane == 2) d_scu[c] = d_cu[g];
        else if (lane == 3) d_sbb[c] = d_bb[g];
    }

    grid_barrier();   // also orders: skey (aliasing sga) dead before phase C writes sga

    // ================= phase C: render 2 tiles per block ============================
#pragma unroll
    for (int it = 0; it < TILES/NBLK; it++) {
        const int tile = bid + it * NBLK;    // distant pairing for load balance
        const int tx = tile & (NTX-1);
        const int ty = tile / NTX;

        const float xmin = (tx*RTW         - 63.5f) * (1.0f/128.0f);
        const float xmax = (tx*RTW + RTW-1 - 63.5f) * (1.0f/128.0f);
        const float ymin = (ty*RTH         - 63.5f) * (1.0f/128.0f);
        const float ymax = (ty*RTH + RTH-1 - 63.5f) * (1.0f/128.0f);

        // ---- order-preserving compaction + fused staging ----
        int base = 0;
#pragma unroll
        for (int p = 0; p < NG/BT; p++) {            // 4 passes, uniform
            int i = p*BT + t;
            float4 cv = d_scu[i];
            bool keep = (cv.x - cv.z <= xmax) && (cv.x + cv.z >= xmin) &&
                        (cv.y - cv.w <= ymax) && (cv.y + cv.w >= ymin);
            unsigned m = __ballot_sync(0xFFFFFFFFu, keep);
            int wofs = __popc(m & ((1u << lane) - 1u));
            if (lane == 0) warpcnt[wid] = __popc(m);
            __syncthreads();
            if (t < 32) {                             // warp 0, full mask
                int v = (t < WPB) ? warpcnt[t] : 0;
#pragma unroll
                for (int o = 1; o < 32; o <<= 1) {
                    int u2 = __shfl_up_sync(0xFFFFFFFFu, v, o);
                    if (lane >= o) v += u2;
                }
                if (t < WPB) warpcnt[t] = v;          // inclusive scan
            }
            __syncthreads();
            int slot = base + (wid ? warpcnt[wid-1] : 0) + wofs;
            if (keep && slot < NCAP) {
                sga[slot] = d_sga[i];
                sgb[slot] = d_sgb[i];
                sbb[slot] = d_sbb[i];
            }
            base += warpcnt[WPB-1];
            __syncthreads();
        }
        const int N = (base < NCAP) ? base : NCAP;

        // ---- chunked branch-free composite ----
        const int sub = t >> 6;             // 0..7
        const int pix = t & (RPPT-1);       // 0..63
        const int x = tx*RTW + (pix & (RTW-1));
        const int y = ty*RTH + (pix >> 3);
        const float px = (x - 63.5f) * (1.0f/128.0f);
        const float py = (y - 63.5f) * (1.0f/128.0f);

        const int Nc = (N + RNSUB - 1) / RNSUB;
        const int k0 = sub * Nc;
        int k1 = k0 + Nc; if (k1 > N) k1 = N;

        float T = 1.0f, cr = 0.0f, cg = 0.0f, cb = 0.0f;
#pragma unroll 4
        for (int k = k0; k < k1; k++) {
            float4 ga = sga[k];
            float4 gb = sgb[k];
            float dx = px - ga.x;
            float dy = py - ga.y;
            float pw = fmaf(fmaf(ga.z, dx, ga.w * dy), dx, fmaf(gb.x * dy, dy, gb.y));
            float al = fminf(__expf(pw), 0.99f);
            float wg = T * al;
            cr = fmaf(wg, gb.z, cr);
            cg = fmaf(wg, gb.w, cg);
            cb = fmaf(wg, sbb[k], cb);
            T -= wg;
        }
        part[sub * RPPT + pix] = make_float4(cr, cg, cb, T);
        __syncthreads();

        // ---- exact recombination + store ----
        if (t < RPPT) {
            float P = 1.0f, r = 0.0f, g = 0.0f, b = 0.0f;
#pragma unroll
            for (int s = 0; s < RNSUB; s++) {
                float4 qq = part[s * RPPT + t];
                r = fmaf(P, qq.x, r);
                g = fmaf(P, qq.y, g);
                b = fmaf(P, qq.z, b);
                P *= qq.w;
            }
            int xx = tx*RTW + (t & (RTW-1));
            int yy = ty*RTH + (t >> 3);
            int o = (yy * W + xx) * 3;
            out[o + 0] = r;
            out[o + 1] = g;
            out[o + 2] = b;
        }
        __syncthreads();   // smem reuse safe before next tile
    }
}

extern "C" void kernel_launch(void* const* d_in, const int* in_sizes, int n_in,
                              void* d_out, int out_size)
{
    const float* pos   = (const float*)d_in[0];
    const float* rgb   = (const float*)d_in[1];
    const float* opa   = (const float*)d_in[2];
    const float* quat  = (const float*)d_in[3];
    const float* scale = (const float*)d_in[4];
    const float* rot   = (const float*)d_in[5];
    const float* tran  = (const float*)d_in[6];
    float* out = (float*)d_out;

    splat_kernel<<<NBLK, BT>>>(pos, rgb, opa, quat, scale, rot, tran, out);
}

// round 11
// speedup vs baseline: 1.5496x; 1.5216x over previous
#include <cuda_runtime.h>
#include <math.h>

#define NG    2048
#define W     128
#define H     128
#define EPSV  1e-4f
#define NEARV 0.3f
#define TAU   12.0f       // cull threshold on folded exponent (err ~e^-12 per gaussian)

// render tiling: 8x8 px tiles, 256 blocks x 1024 threads, 16 depth chunks
#define RTW   8
#define RTH   8
#define RPPT  (RTW*RTH)    // 64 px
#define RNSUB 16           // depth chunks
#define RBT   (RNSUB*RPPT) // 1024 threads
#define NTX   (W/RTW)      // 16
#define NTY   (H/RTH)      // 16
#define NCAP  1024         // survivor cap (generous)

// ---------------- device scratch ----------------
__device__ float4 d_ga [NG];   // u, v, A, B
__device__ float4 d_gb [NG];   // C, L, r, g
__device__ float4 d_cu [NG];   // u, v, hx, hy
__device__ float  d_bb [NG];   // b
__device__ float  d_key[NG];   // depth key

__device__ __forceinline__ float sigmoidf_(float x) {
    return 1.0f / (1.0f + expf(-x));
}

// ---------------- 1) per-gaussian preprocessing ----------------
__global__ void __launch_bounds__(64) prep_kernel(
        const float* __restrict__ pos,
        const float* __restrict__ rgb,
        const float* __restrict__ opa,
        const float* __restrict__ quat,
        const float* __restrict__ scale,
        const float* __restrict__ rot,
        const float* __restrict__ tran)
{
    int n = blockIdx.x * 64 + threadIdx.x;
    if (n >= NG) return;

    float Rw[9];
#pragma unroll
    for (int i = 0; i < 9; i++) Rw[i] = __ldg(&rot[i]);
    float t0 = __ldg(&tran[0]), t1 = __ldg(&tran[1]), t2 = __ldg(&tran[2]);

    float p0 = __ldg(&pos[n*3+0]), p1 = __ldg(&pos[n*3+1]), p2 = __ldg(&pos[n*3+2]);
    float x = Rw[0]*p0 + Rw[1]*p1 + Rw[2]*p2 + t0;
    float y = Rw[3]*p0 + Rw[4]*p1 + Rw[5]*p2 + t1;
    float z = Rw[6]*p0 + Rw[7]*p1 + Rw[8]*p2 + t2;

    float r = sqrtf(x*x + y*y + z*z);
    float iz  = 1.0f / z;
    float u = x * iz, v = y * iz;
    float iz2 = iz * iz;

    float M00 = iz*Rw[0] - x*iz2*Rw[6];
    float M01 = iz*Rw[1] - x*iz2*Rw[7];
    float M02 = iz*Rw[2] - x*iz2*Rw[8];
    float M10 = iz*Rw[3] - y*iz2*Rw[6];
    float M11 = iz*Rw[4] - y*iz2*Rw[7];
    float M12 = iz*Rw[5] - y*iz2*Rw[8];

    float4 q4 = __ldg((const float4*)(quat + n*4));
    float qw = q4.x, qx = q4.y, qy = q4.z, qz = q4.w;
    float qn = rsqrtf(qw*qw + qx*qx + qy*qy + qz*qz);
    qw *= qn; qx *= qn; qy *= qn; qz *= qn;
    float R00 = 1.0f - 2.0f*(qy*qy + qz*qz);
    float R01 = 2.0f*(qx*qy - qw*qz);
    float R02 = 2.0f*(qx*qz + qw*qy);
    float R10 = 2.0f*(qx*qy + qw*qz);
    float R11 = 1.0f - 2.0f*(qx*qx + qz*qz);
    float R12 = 2.0f*(qy*qz - qw*qx);
    float R20 = 2.0f*(qx*qz - qw*qy);
    float R21 = 2.0f*(qy*qz + qw*qx);
    float R22 = 1.0f - 2.0f*(qx*qx + qy*qy);

    float s0 = fabsf(__ldg(&scale[n*3+0])) + 1e-4f;
    float s1 = fabsf(__ldg(&scale[n*3+1])) + 1e-4f;
    float s2 = fabsf(__ldg(&scale[n*3+2])) + 1e-4f;
    float q0 = s0*s0, q1 = s1*s1, q2 = s2*s2;

    float c00 = R00*R00*q0 + R01*R01*q1 + R02*R02*q2;
    float c01 = R00*R10*q0 + R01*R11*q1 + R02*R12*q2;
    float c02 = R00*R20*q0 + R01*R21*q1 + R02*R22*q2;
    float c11 = R10*R10*q0 + R11*R11*q1 + R12*R12*q2;
    float c12 = R10*R20*q0 + R11*R21*q1 + R12*R22*q2;
    float c22 = R20*R20*q0 + R21*R21*q1 + R22*R22*q2;

    float v00 = c00*M00 + c01*M01 + c02*M02;
    float v01 = c01*M00 + c11*M01 + c12*M02;
    float v02 = c02*M00 + c12*M01 + c22*M02;
    float v10 = c00*M10 + c01*M11 + c02*M12;
    float v11 = c01*M10 + c11*M11 + c12*M12;
    float v12 = c02*M10 + c12*M11 + c22*M12;

    float a  = M00*v00 + M01*v01 + M02*v02 + EPSV;   // Sigma_xx
    float b  = M00*v10 + M01*v11 + M02*v12;
    float cc = M10*v10 + M11*v11 + M12*v12 + EPSV;   // Sigma_yy

    float det  = a*cc - b*b;
    float idet = 1.0f / det;
    float A = -0.5f * cc * idet;
    float B =  b * idet;
    float C = -0.5f * a  * idet;

    float opa_s = sigmoidf_(__ldg(&opa[n]));
    float L = (z > NEARV) ? logf(opa_s) : -1e30f;

    float tau = TAU + L;
    float hx, hy;
    if (tau > 0.0f) {
        hx = sqrtf(2.0f * tau * a);
        hy = sqrtf(2.0f * tau * cc);
    } else {
        hx = -1e30f; hy = -1e30f;   // always culled
    }

    float cr = sigmoidf_(__ldg(&rgb[n*3+0]));
    float cg = sigmoidf_(__ldg(&rgb[n*3+1]));
    float cb = sigmoidf_(__ldg(&rgb[n*3+2]));

    d_cu [n] = make_float4(u, v, hx, hy);
    d_ga [n] = make_float4(u, v, A, B);
    d_gb [n] = make_float4(C, L, cr, cg);
    d_bb [n] = cb;
    d_key[n] = r;
}

// ---------------- 2) per-tile cull + parallel rank-sort + composite ----------------
extern __shared__ char smx[];
// layout: kidx int[NCAP] 4KB | kr float[NCAP] 4KB | sga float4[NCAP] 16KB |
//         sgb float4[NCAP] 16KB | sbb float[NCAP] 4KB | part float4[RNSUB*RPPT] 16KB
#define O_KIDX 0
#define O_KR   (O_KIDX + NCAP*4)
#define O_SGA  (O_KR   + NCAP*4)
#define O_SGB  (O_SGA  + NCAP*16)
#define O_SBB  (O_SGB  + NCAP*16)
#define O_PART (O_SBB  + NCAP*4)
#define RSMEM  (O_PART + RNSUB*RPPT*16)   // 60KB

__global__ void __launch_bounds__(RBT, 1) render_kernel(float* __restrict__ out)
{
    int*    kidx = (int*   )(smx + O_KIDX);
    float*  kr   = (float* )(smx + O_KR);
    float4* sga  = (float4*)(smx + O_SGA);
    float4* sgb  = (float4*)(smx + O_SGB);
    float*  sbb  = (float* )(smx + O_SBB);
    float4* part = (float4*)(smx + O_PART);
    __shared__ int scnt;

    const int t  = threadIdx.x;
    const int tx = blockIdx.x, ty = blockIdx.y;

    if (t == 0) scnt = 0;
    __syncthreads();

    const float xmin = (tx*RTW         - 63.5f) * (1.0f/128.0f);
    const float xmax = (tx*RTW + RTW-1 - 63.5f) * (1.0f/128.0f);
    const float ymin = (ty*RTH         - 63.5f) * (1.0f/128.0f);
    const float ymax = (ty*RTH + RTH-1 - 63.5f) * (1.0f/128.0f);

    // ---- cull: unordered atomic collect (order fixed by sort below) ----
#pragma unroll
    for (int p = 0; p < NG/RBT; p++) {
        int i = p*RBT + t;
        float4 cv = __ldg(&d_cu[i]);
        bool keep = (cv.x - cv.z <= xmax) && (cv.x + cv.z >= xmin) &&
                    (cv.y - cv.w <= ymax) && (cv.y + cv.w >= ymin);
        if (keep) {
            int slot = atomicAdd(&scnt, 1);
            if (slot < NCAP) kidx[slot] = i;
        }
    }
    __syncthreads();
    const int N = (scnt < NCAP) ? scnt : NCAP;

    // survivor keys
    for (int i = t; i < N; i += RBT) kr[i] = __ldg(&d_key[kidx[i]]);
    __syncthreads();

    // ---- parallel rank-sort: 4 threads per survivor, uniform rounds ----
    // rank c = #{j : key[j] < key[i]  or  (== and orig_idx[j] < orig_idx[i])}
    {
        const int rounds = (4*N + RBT - 1) / RBT;        // block-uniform
        for (int rd = 0; rd < rounds; rd++) {
            int q = rd*RBT + t;
            int i = q >> 2, h = q & 3;
            int iload = (i < N) ? i : (N - 1);           // N>=1 when rounds>=1
            float ki = kr[iload];
            int   gi = kidx[iload];
            int c = 0;
            for (int j = h; j < N; j += 4) {
                float kj = kr[j];
                c += (int)((kj < ki) | ((kj == ki) & (kidx[j] < gi)));
            }
            c += __shfl_xor_sync(0xFFFFFFFFu, c, 1);     // full-mask, all lanes
            c += __shfl_xor_sync(0xFFFFFFFFu, c, 2);
            if (i < N && h == 0) {
                sga[c] = __ldg(&d_ga[gi]);
                sgb[c] = __ldg(&d_gb[gi]);
                sbb[c] = __ldg(&d_bb[gi]);
            }
        }
    }
    __syncthreads();

    // ---- chunked branch-free composite ----
    const int sub = t >> 6;             // 0..15
    const int pix = t & (RPPT-1);       // 0..63
    const int x = tx*RTW + (pix & (RTW-1));
    const int y = ty*RTH + (pix >> 3);
    const float px = (x - 63.5f) * (1.0f/128.0f);
    const float py = (y - 63.5f) * (1.0f/128.0f);

    const int Nc = (N + RNSUB - 1) / RNSUB;
    const int k0 = sub * Nc;
    int k1 = k0 + Nc; if (k1 > N) k1 = N;

    float T = 1.0f, cr = 0.0f, cg = 0.0f, cb = 0.0f;
#pragma unroll 4
    for (int k = k0; k < k1; k++) {
        float4 ga = sga[k];
        float4 gb = sgb[k];
        float dx = px - ga.x;
        float dy = py - ga.y;
        float pw = fmaf(fmaf(ga.z, dx, ga.w * dy), dx, fmaf(gb.x * dy, dy, gb.y));
        float al = fminf(__expf(pw), 0.99f);
        float wg = T * al;
        cr = fmaf(wg, gb.z, cr);
        cg = fmaf(wg, gb.w, cg);
        cb = fmaf(wg, sbb[k], cb);
        T -= wg;
    }
    part[sub * RPPT + pix] = make_float4(cr, cg, cb, T);
    __syncthreads();

    // ---- exact recombination + store ----
    if (t < RPPT) {
        float P = 1.0f, r = 0.0f, g = 0.0f, b = 0.0f;
#pragma unroll
        for (int s = 0; s < RNSUB; s++) {
            float4 qq = part[s * RPPT + t];
            r = fmaf(P, qq.x, r);
            g = fmaf(P, qq.y, g);
            b = fmaf(P, qq.z, b);
            P *= qq.w;
        }
        int xx = tx*RTW + (t & (RTW-1));
        int yy = ty*RTH + (t >> 3);
        int o = (yy * W + xx) * 3;
        out[o + 0] = r;
        out[o + 1] = g;
        out[o + 2] = b;
    }
}

extern "C" void kernel_launch(void* const* d_in, const int* in_sizes, int n_in,
                              void* d_out, int out_size)
{
    const float* pos   = (const float*)d_in[0];
    const float* rgb   = (const float*)d_in[1];
    const float* opa   = (const float*)d_in[2];
    const float* quat  = (const float*)d_in[3];
    const float* scale = (const float*)d_in[4];
    const float* rot   = (const float*)d_in[5];
    const float* tran  = (const float*)d_in[6];
    float* out = (float*)d_out;

    static int smem_set = 0;
    if (!smem_set) {
        cudaFuncSetAttribute(render_kernel,
                             cudaFuncAttributeMaxDynamicSharedMemorySize,
                             RSMEM);
        smem_set = 1;
    }

    prep_kernel<<<NG/64, 64>>>(pos, rgb, opa, quat, scale, rot, tran);
    render_kernel<<<dim3(NTX, NTY), RBT, RSMEM>>>(out);
}